// round 1
// baseline (speedup 1.0000x reference)
#include <cuda_runtime.h>
#include <math.h>

#define B   4
#define HW  512
#define C0  32
#define CM  64

// ---------------------------------------------------------------------------
// Scratch (allocation-free rule: __device__ globals)
//   bufA: conv1 offsets out -> then reused as conv2 weights-branch out
//   bufB: conv1 weights out
//   bufC: conv2 offsets out
// ---------------------------------------------------------------------------
__device__ __align__(256) float g_bufA[(size_t)B * HW * HW * CM];
__device__ __align__(256) float g_bufB[(size_t)B * HW * HW * CM];
__device__ __align__(256) float g_bufC[(size_t)B * HW * HW * CM];
__device__ int g_cls[B];

// ---------------------------------------------------------------------------
// Head: GAP(f4) -> FC(256,128)+relu -> FC(128,128)+relu -> FC(128,3) ->
// softmax -> pred_cls out + argmax cls to g_cls. One block per batch.
// ---------------------------------------------------------------------------
__global__ void head_kernel(const float* __restrict__ f4,
                            const float* __restrict__ Wc1, const float* __restrict__ bc1,
                            const float* __restrict__ Wc2, const float* __restrict__ bc2,
                            const float* __restrict__ Wc3, const float* __restrict__ bc3,
                            float* __restrict__ out_pred)
{
    __shared__ float gap[256];
    __shared__ float z1[128];
    __shared__ float z2[128];
    __shared__ float logits[3];

    const int b = blockIdx.x;
    const int tid = threadIdx.x;

    // GAP: mean over 32*32 spatial, channel = tid (256 channels, contiguous)
    const float* p = f4 + (size_t)b * 1024 * 256 + tid;
    float s0 = 0.f, s1 = 0.f, s2 = 0.f, s3 = 0.f;
    for (int i = 0; i < 1024; i += 4) {
        s0 += p[(i + 0) * 256];
        s1 += p[(i + 1) * 256];
        s2 += p[(i + 2) * 256];
        s3 += p[(i + 3) * 256];
    }
    gap[tid] = (s0 + s1 + s2 + s3) * (1.0f / 1024.0f);
    __syncthreads();

    if (tid < 128) {
        float a = bc1[tid];
#pragma unroll 8
        for (int k = 0; k < 256; ++k) a = fmaf(gap[k], Wc1[k * 128 + tid], a);
        z1[tid] = fmaxf(a, 0.f);
    }
    __syncthreads();

    if (tid < 128) {
        float a = bc2[tid];
#pragma unroll 8
        for (int k = 0; k < 128; ++k) a = fmaf(z1[k], Wc2[k * 128 + tid], a);
        z2[tid] = fmaxf(a, 0.f);
    }
    __syncthreads();

    if (tid < 3) {
        float a = bc3[tid];
        for (int k = 0; k < 128; ++k) a = fmaf(z2[k], Wc3[k * 3 + tid], a);
        logits[tid] = a;
    }
    __syncthreads();

    if (tid == 0) {
        float l0 = logits[0], l1 = logits[1], l2 = logits[2];
        float m = fmaxf(l0, fmaxf(l1, l2));
        float e0 = expf(l0 - m), e1 = expf(l1 - m), e2 = expf(l2 - m);
        float inv = 1.f / (e0 + e1 + e2);
        out_pred[b * 3 + 0] = e0 * inv;
        out_pred[b * 3 + 1] = e1 * inv;
        out_pred[b * 3 + 2] = e2 * inv;
        // argmax (first-max semantics, same order as softmax argmax)
        int c = 0; float best = l0;
        if (l1 > best) { best = l1; c = 1; }
        if (l2 > best) { best = l2; c = 2; }
        g_cls[b] = c;
    }
}

// ---------------------------------------------------------------------------
// 3x3 SAME conv, CIN -> 64 channels, ReLU. Implicit-GEMM tiling:
//   block = 16x16 pixel tile, 256 threads, each thread 8px x 8co register tile.
//   in_s : (16+2) rows x (16+2) cols x CIN, row pitch padded +4 floats
//          (makes the 4 row-distinct addresses per LDS land in distinct banks)
//   w_s  : [9][16ci][64co] chunk of weights, reloaded per 16-ci chunk.
// FFMA-issue bound by design (64 FFMA : ~10 LDS per inner step).
// ---------------------------------------------------------------------------
template <int CIN>
__global__ void __launch_bounds__(256, 1)
conv3x3_relu64(const float* __restrict__ in, const float* __restrict__ w,
               const float* __restrict__ bias, float* __restrict__ out)
{
    constexpr int RP = 18 * CIN + 4;   // padded row pitch (floats)
    extern __shared__ float smem[];
    float* in_s = smem;                 // 18 * RP floats
    float* w_s  = smem + 18 * RP;       // 9 * 16 * 64 floats

    const int b  = blockIdx.z;
    const int y0 = blockIdx.y * 16;
    const int x0 = blockIdx.x * 16;
    const int tid = threadIdx.x;

    // --- cooperative input tile load (zero-pad SAME borders), float4 over ci
    const float* inb = in + (size_t)b * HW * HW * CIN;
    const int NV = 18 * 18 * (CIN / 4);
    for (int i = tid; i < NV; i += 256) {
        int ci4 = i % (CIN / 4);
        int rc  = i / (CIN / 4);
        int r = rc / 18, c = rc % 18;
        int gy = y0 + r - 1, gx = x0 + c - 1;
        float4 v = make_float4(0.f, 0.f, 0.f, 0.f);
        if ((unsigned)gy < HW && (unsigned)gx < HW)
            v = *(const float4*)&inb[((size_t)gy * HW + gx) * CIN + ci4 * 4];
        *(float4*)&in_s[r * RP + c * CIN + ci4 * 4] = v;
    }

    const int tx  = tid & 7;        // 8 co-groups -> co = tx*8 .. tx*8+7
    const int ty  = tid >> 3;       // 0..31
    const int row = ty & 15;        // pixel row within tile
    const int c0  = (ty >> 4) * 8;  // pixel col base (8 consecutive cols)

    float acc[8][8];
#pragma unroll
    for (int p = 0; p < 8; ++p)
#pragma unroll
        for (int c = 0; c < 8; ++c) acc[p][c] = 0.f;

    for (int ci0 = 0; ci0 < CIN; ci0 += 16) {
        __syncthreads();  // protect in_s (first iter) / w_s (later iters)
        // --- load weight chunk [9][16][64] : HWIO layout ((k*CIN+ci)*64+co)
        for (int i = tid; i < 9 * 16 * 16; i += 256) {
            int co4 = i & 15;
            int kci = i >> 4;            // k*16 + ci, 0..143
            int k   = kci >> 4;
            int ci  = kci & 15;
            *(float4*)&w_s[kci * 64 + co4 * 4] =
                *(const float4*)&w[((size_t)(k * CIN + ci0 + ci)) * 64 + co4 * 4];
        }
        __syncthreads();

#pragma unroll 1
        for (int ky = 0; ky < 3; ++ky) {
#pragma unroll 1
            for (int kx = 0; kx < 3; ++kx) {
                const float* ain = &in_s[(row + ky) * RP + (c0 + kx) * CIN + ci0];
                const float* wbs = &w_s[(ky * 3 + kx) * 16 * 64 + tx * 8];
#pragma unroll
                for (int ci = 0; ci < 16; ++ci) {
                    float a[8];
#pragma unroll
                    for (int p = 0; p < 8; ++p) a[p] = ain[p * CIN + ci];
                    float4 b0 = *(const float4*)&wbs[ci * 64];
                    float4 b1 = *(const float4*)&wbs[ci * 64 + 4];
#pragma unroll
                    for (int p = 0; p < 8; ++p) {
                        acc[p][0] = fmaf(a[p], b0.x, acc[p][0]);
                        acc[p][1] = fmaf(a[p], b0.y, acc[p][1]);
                        acc[p][2] = fmaf(a[p], b0.z, acc[p][2]);
                        acc[p][3] = fmaf(a[p], b0.w, acc[p][3]);
                        acc[p][4] = fmaf(a[p], b1.x, acc[p][4]);
                        acc[p][5] = fmaf(a[p], b1.y, acc[p][5]);
                        acc[p][6] = fmaf(a[p], b1.z, acc[p][6]);
                        acc[p][7] = fmaf(a[p], b1.w, acc[p][7]);
                    }
                }
            }
        }
    }

    float bv[8];
#pragma unroll
    for (int c = 0; c < 8; ++c) bv[c] = bias[tx * 8 + c];

#pragma unroll
    for (int p = 0; p < 8; ++p) {
        size_t o = (((size_t)b * HW + (y0 + row)) * HW + (x0 + c0 + p)) * 64 + tx * 8;
        float4 v0, v1;
        v0.x = fmaxf(acc[p][0] + bv[0], 0.f);
        v0.y = fmaxf(acc[p][1] + bv[1], 0.f);
        v0.z = fmaxf(acc[p][2] + bv[2], 0.f);
        v0.w = fmaxf(acc[p][3] + bv[3], 0.f);
        v1.x = fmaxf(acc[p][4] + bv[4], 0.f);
        v1.y = fmaxf(acc[p][5] + bv[5], 0.f);
        v1.z = fmaxf(acc[p][6] + bv[6], 0.f);
        v1.w = fmaxf(acc[p][7] + bv[7], 0.f);
        *(float4*)&out[o]     = v0;
        *(float4*)&out[o + 4] = v1;
    }
}

// ---------------------------------------------------------------------------
// Final convs fused with the channel gather: only the selected channels
// (offsets: 2*cls, 2*cls+1 from Wo3; weights: cls from Ww3) are computed.
// Tiles held channel-major in smem so lanes (consecutive x) hit consecutive
// banks. Writes the final d_out layout directly.
// ---------------------------------------------------------------------------
__global__ void __launch_bounds__(256, 1)
conv3_select(const float* __restrict__ h2o, const float* __restrict__ h2w,
             const float* __restrict__ Wo3, const float* __restrict__ bo3,
             const float* __restrict__ Ww3, const float* __restrict__ bw3,
             float* __restrict__ out)
{
    extern __shared__ float smem[];
    float* ho = smem;                 // 64 * 342  (ci-major, pitch 19 per row)
    float* hw = smem + 64 * 342;      // 64 * 342
    float* ws = smem + 2 * 64 * 342;  // 576 * 3 selected weights

    const int b   = blockIdx.z;
    const int y0  = blockIdx.y * 16;
    const int x0  = blockIdx.x * 16;
    const int tid = threadIdx.x;
    const int cls = g_cls[b];

    // selected weight slices: Wo3 (3,3,64,6), Ww3 (3,3,64,3)
    for (int i = tid; i < 576; i += 256) {
        ws[i * 3 + 0] = Wo3[i * 6 + 2 * cls];
        ws[i * 3 + 1] = Wo3[i * 6 + 2 * cls + 1];
        ws[i * 3 + 2] = Ww3[i * 3 + cls];
    }

    // load both input tiles (18x18x64) transposed to [ci][r*19+c]
    const float* po = h2o + (size_t)b * HW * HW * 64;
    const float* pw = h2w + (size_t)b * HW * HW * 64;
    for (int i = tid; i < 324 * 16; i += 256) {
        int ci4 = i & 15;
        int rc  = i >> 4;
        int r = rc / 18, c = rc % 18;
        int gy = y0 + r - 1, gx = x0 + c - 1;
        float4 vo = make_float4(0.f, 0.f, 0.f, 0.f);
        float4 vw = vo;
        if ((unsigned)gy < HW && (unsigned)gx < HW) {
            size_t g = ((size_t)gy * HW + gx) * 64 + ci4 * 4;
            vo = *(const float4*)&po[g];
            vw = *(const float4*)&pw[g];
        }
        int base = r * 19 + c;
        ho[(ci4 * 4 + 0) * 342 + base] = vo.x;
        ho[(ci4 * 4 + 1) * 342 + base] = vo.y;
        ho[(ci4 * 4 + 2) * 342 + base] = vo.z;
        ho[(ci4 * 4 + 3) * 342 + base] = vo.w;
        hw[(ci4 * 4 + 0) * 342 + base] = vw.x;
        hw[(ci4 * 4 + 1) * 342 + base] = vw.y;
        hw[(ci4 * 4 + 2) * 342 + base] = vw.z;
        hw[(ci4 * 4 + 3) * 342 + base] = vw.w;
    }
    __syncthreads();

    const int r = tid >> 4, c = tid & 15;
    float o0 = bo3[2 * cls], o1 = bo3[2 * cls + 1], wv = bw3[cls];

#pragma unroll 1
    for (int ky = 0; ky < 3; ++ky) {
#pragma unroll 1
        for (int kx = 0; kx < 3; ++kx) {
            int base = (r + ky) * 19 + (c + kx);
            const float* wp = &ws[(ky * 3 + kx) * 64 * 3];
#pragma unroll 8
            for (int ci = 0; ci < 64; ++ci) {
                float ao = ho[ci * 342 + base];
                float aw = hw[ci * 342 + base];
                o0 = fmaf(ao, wp[ci * 3 + 0], o0);
                o1 = fmaf(ao, wp[ci * 3 + 1], o1);
                wv = fmaf(aw, wp[ci * 3 + 2], wv);
            }
        }
    }

    int gy = y0 + r, gx = x0 + c;
    size_t pix = ((size_t)b * HW + gy) * HW + gx;
    *(float2*)&out[pix * 2] = make_float2(o0, o1);                 // offsets
    out[(size_t)B * HW * HW * 2 + pix] = wv;                       // weights
}

// ---------------------------------------------------------------------------
extern "C" void kernel_launch(void* const* d_in, const int* in_sizes, int n_in,
                              void* d_out, int out_size)
{
    (void)in_sizes; (void)n_in; (void)out_size;
    const float* x0  = (const float*)d_in[0];
    const float* f4  = (const float*)d_in[1];
    const float* Wo1 = (const float*)d_in[2];
    const float* bo1 = (const float*)d_in[3];
    const float* Wo2 = (const float*)d_in[4];
    const float* bo2 = (const float*)d_in[5];
    const float* Wo3 = (const float*)d_in[6];
    const float* bo3 = (const float*)d_in[7];
    const float* Ww1 = (const float*)d_in[8];
    const float* bw1 = (const float*)d_in[9];
    const float* Ww2 = (const float*)d_in[10];
    const float* bw2 = (const float*)d_in[11];
    const float* Ww3 = (const float*)d_in[12];
    const float* bw3 = (const float*)d_in[13];
    const float* Wc1 = (const float*)d_in[14];
    const float* bc1 = (const float*)d_in[15];
    const float* Wc2 = (const float*)d_in[16];
    const float* bc2 = (const float*)d_in[17];
    const float* Wc3 = (const float*)d_in[18];
    const float* bc3 = (const float*)d_in[19];
    float* out = (float*)d_out;

    void *pA, *pB, *pC;
    cudaGetSymbolAddress(&pA, g_bufA);
    cudaGetSymbolAddress(&pB, g_bufB);
    cudaGetSymbolAddress(&pC, g_bufC);
    float* bufA = (float*)pA;
    float* bufB = (float*)pB;
    float* bufC = (float*)pC;

    const size_t smem32 = (size_t)(18 * (18 * 32 + 4) + 9 * 16 * 64) * sizeof(float); //  78.9 KB
    const size_t smem64 = (size_t)(18 * (18 * 64 + 4) + 9 * 16 * 64) * sizeof(float); // 120.1 KB
    const size_t smem3  = (size_t)(2 * 64 * 342 + 576 * 3) * sizeof(float);           // 182.0 KB

    cudaFuncSetAttribute(conv3x3_relu64<32>, cudaFuncAttributeMaxDynamicSharedMemorySize, (int)smem32);
    cudaFuncSetAttribute(conv3x3_relu64<64>, cudaFuncAttributeMaxDynamicSharedMemorySize, (int)smem64);
    cudaFuncSetAttribute(conv3_select,       cudaFuncAttributeMaxDynamicSharedMemorySize, (int)smem3);

    // pred_cls tail of d_out: offsets (B*HW*HW*2) + weights (B*HW*HW)
    float* pred = out + (size_t)B * HW * HW * 3;

    head_kernel<<<B, 256>>>(f4, Wc1, bc1, Wc2, bc2, Wc3, bc3, pred);

    dim3 grid(HW / 16, HW / 16, B);
    conv3x3_relu64<32><<<grid, 256, smem32>>>(x0, Wo1, bo1, bufA);   // offsets L1
    conv3x3_relu64<32><<<grid, 256, smem32>>>(x0, Ww1, bw1, bufB);   // weights L1
    conv3x3_relu64<64><<<grid, 256, smem64>>>(bufA, Wo2, bo2, bufC); // offsets L2
    conv3x3_relu64<64><<<grid, 256, smem64>>>(bufB, Ww2, bw2, bufA); // weights L2 (reuses A)
    conv3_select<<<grid, 256, smem3>>>(bufC, bufA, Wo3, bo3, Ww3, bw3, out);
}

// round 2
// speedup vs baseline: 1.0278x; 1.0278x over previous
#include <cuda_runtime.h>
#include <math.h>

#define B   4
#define HW  512
#define C0  32
#define CM  64

typedef unsigned long long ull;

// ---------------------------------------------------------------------------
// Scratch (allocation-free rule: __device__ globals)
// ---------------------------------------------------------------------------
__device__ __align__(256) float g_bufA[(size_t)B * HW * HW * CM];
__device__ __align__(256) float g_bufB[(size_t)B * HW * HW * CM];
__device__ __align__(256) float g_bufC[(size_t)B * HW * HW * CM];
__device__ int g_cls[B];

// packed f32x2 FMA: d = a*b + c elementwise on two fp32 lanes in a 64-bit reg
__device__ __forceinline__ ull ffma2(ull a, ull b, ull c) {
    ull d;
    asm("fma.rn.f32x2 %0, %1, %2, %3;" : "=l"(d) : "l"(a), "l"(b), "l"(c));
    return d;
}
__device__ __forceinline__ ull pack2(float lo, float hi) {
    union { float2 f; ull u; } v;
    v.f = make_float2(lo, hi);
    return v.u;
}
__device__ __forceinline__ float2 unpack2(ull u) {
    union { float2 f; ull u; } v;
    v.u = u;
    return v.f;
}

// ---------------------------------------------------------------------------
// Head: GAP(f4) -> FC chain -> softmax -> pred_cls + argmax cls
// ---------------------------------------------------------------------------
__global__ void head_kernel(const float* __restrict__ f4,
                            const float* __restrict__ Wc1, const float* __restrict__ bc1,
                            const float* __restrict__ Wc2, const float* __restrict__ bc2,
                            const float* __restrict__ Wc3, const float* __restrict__ bc3,
                            float* __restrict__ out_pred)
{
    __shared__ float gap[256];
    __shared__ float z1[128];
    __shared__ float z2[128];
    __shared__ float logits[3];

    const int b = blockIdx.x;
    const int tid = threadIdx.x;

    const float* p = f4 + (size_t)b * 1024 * 256 + tid;
    float s0 = 0.f, s1 = 0.f, s2 = 0.f, s3 = 0.f;
    for (int i = 0; i < 1024; i += 4) {
        s0 += p[(i + 0) * 256];
        s1 += p[(i + 1) * 256];
        s2 += p[(i + 2) * 256];
        s3 += p[(i + 3) * 256];
    }
    gap[tid] = (s0 + s1 + s2 + s3) * (1.0f / 1024.0f);
    __syncthreads();

    if (tid < 128) {
        float a = bc1[tid];
#pragma unroll 8
        for (int k = 0; k < 256; ++k) a = fmaf(gap[k], Wc1[k * 128 + tid], a);
        z1[tid] = fmaxf(a, 0.f);
    }
    __syncthreads();

    if (tid < 128) {
        float a = bc2[tid];
#pragma unroll 8
        for (int k = 0; k < 128; ++k) a = fmaf(z1[k], Wc2[k * 128 + tid], a);
        z2[tid] = fmaxf(a, 0.f);
    }
    __syncthreads();

    if (tid < 3) {
        float a = bc3[tid];
        for (int k = 0; k < 128; ++k) a = fmaf(z2[k], Wc3[k * 3 + tid], a);
        logits[tid] = a;
    }
    __syncthreads();

    if (tid == 0) {
        float l0 = logits[0], l1 = logits[1], l2 = logits[2];
        float m = fmaxf(l0, fmaxf(l1, l2));
        float e0 = expf(l0 - m), e1 = expf(l1 - m), e2 = expf(l2 - m);
        float inv = 1.f / (e0 + e1 + e2);
        out_pred[b * 3 + 0] = e0 * inv;
        out_pred[b * 3 + 1] = e1 * inv;
        out_pred[b * 3 + 2] = e2 * inv;
        int c = 0; float best = l0;
        if (l1 > best) { best = l1; c = 1; }
        if (l2 > best) { best = l2; c = 2; }
        g_cls[b] = c;
    }
}

// ---------------------------------------------------------------------------
// 3x3 SAME conv, CIN -> 64, ReLU.  FFMA2 version.
//   block = 16x16 px tile, 256 threads, thread = 8px x 8co.
//   in_s : [18*18 pixels][2*CIN dup + 2 pad]  -- each value stored as (a,a)
//          so the activation operand of fma.f32x2 is a single LDS.64.
//   w_s  : [9][16ci][64co] chunk; (w[c],w[c+1]) pairs come straight out of
//          LDS.128 as aligned register pairs (zero pack instructions).
//   Inner: per (ky,ci) load 10 activation dup-pairs once, reuse across kx.
//          96 FFMA2 (=192 FMA) per 16 LDS.
// ---------------------------------------------------------------------------
template <int CIN>
__global__ void __launch_bounds__(256, 1)
conv3x3_relu64(const float* __restrict__ in, const float* __restrict__ w,
               const float* __restrict__ bias, float* __restrict__ out)
{
    constexpr int STRIDE = 2 * CIN + 2;          // floats per pixel (dup + pad)
    extern __shared__ float smem[];
    float* in_s = smem;                           // 324 * STRIDE floats
    float* w_s  = smem + 324 * STRIDE;            // 9 * 16 * 64 floats

    const int b  = blockIdx.z;
    const int y0 = blockIdx.y * 16;
    const int x0 = blockIdx.x * 16;
    const int tid = threadIdx.x;

    // --- cooperative input tile load with duplication: (v, v) pairs
    const float* inb = in + (size_t)b * HW * HW * CIN;
    const int NV = 324 * (CIN / 4);
    for (int i = tid; i < NV; i += 256) {
        int ci4 = i % (CIN / 4);
        int pix = i / (CIN / 4);
        int r = pix / 18, c = pix % 18;
        int gy = y0 + r - 1, gx = x0 + c - 1;
        float4 v = make_float4(0.f, 0.f, 0.f, 0.f);
        if ((unsigned)gy < HW && (unsigned)gx < HW)
            v = *(const float4*)&inb[((size_t)gy * HW + gx) * CIN + ci4 * 4];
        ull* dst = (ull*)&in_s[pix * STRIDE + ci4 * 8];
        dst[0] = pack2(v.x, v.x);
        dst[1] = pack2(v.y, v.y);
        dst[2] = pack2(v.z, v.z);
        dst[3] = pack2(v.w, v.w);
    }

    const int tx  = tid & 7;        // co group: co = tx*8 .. tx*8+7
    const int ty  = tid >> 3;
    const int row = ty & 15;        // pixel row in tile
    const int c0  = (ty >> 4) * 8;  // pixel col base

    ull acc[8][4];                  // [pixel p][co pair]
#pragma unroll
    for (int p = 0; p < 8; ++p)
#pragma unroll
        for (int q = 0; q < 4; ++q) acc[p][q] = 0ull;

    for (int ci0 = 0; ci0 < CIN; ci0 += 16) {
        __syncthreads();
        // --- weight chunk [9][16][64], HWIO: w[((k*CIN+ci))*64 + co]
        for (int i = tid; i < 9 * 16 * 16; i += 256) {
            int co4 = i & 15;
            int kci = i >> 4;
            int k   = kci >> 4;
            int ci  = kci & 15;
            *(float4*)&w_s[kci * 64 + co4 * 4] =
                *(const float4*)&w[((size_t)(k * CIN + ci0 + ci)) * 64 + co4 * 4];
        }
        __syncthreads();

#pragma unroll 1
        for (int ky = 0; ky < 3; ++ky) {
            const int rbase = (row + ky) * 18 + c0;
#pragma unroll 2
            for (int ci = 0; ci < 16; ++ci) {
                const int cidx = (ci0 + ci) * 2;
                // 10 activation dup-pairs: pixels c0 .. c0+9 of this row
                ull a[10];
#pragma unroll
                for (int j = 0; j < 10; ++j)
                    a[j] = *(const ull*)&in_s[(rbase + j) * STRIDE + cidx];

#pragma unroll
                for (int kx = 0; kx < 3; ++kx) {
                    const float* wb = &w_s[((ky * 3 + kx) * 16 + ci) * 64 + tx * 8];
                    ulonglong2 w01 = *(const ulonglong2*)&wb[0];  // (w0,w1),(w2,w3)
                    ulonglong2 w23 = *(const ulonglong2*)&wb[4];  // (w4,w5),(w6,w7)
#pragma unroll
                    for (int p = 0; p < 8; ++p) {
                        ull ap = a[p + kx];
                        acc[p][0] = ffma2(ap, w01.x, acc[p][0]);
                        acc[p][1] = ffma2(ap, w01.y, acc[p][1]);
                        acc[p][2] = ffma2(ap, w23.x, acc[p][2]);
                        acc[p][3] = ffma2(ap, w23.y, acc[p][3]);
                    }
                }
            }
        }
    }

    float bv[8];
#pragma unroll
    for (int c = 0; c < 8; ++c) bv[c] = bias[tx * 8 + c];

#pragma unroll
    for (int p = 0; p < 8; ++p) {
        size_t o = (((size_t)b * HW + (y0 + row)) * HW + (x0 + c0 + p)) * 64 + tx * 8;
        float2 a0 = unpack2(acc[p][0]);
        float2 a1 = unpack2(acc[p][1]);
        float2 a2 = unpack2(acc[p][2]);
        float2 a3 = unpack2(acc[p][3]);
        float4 v0, v1;
        v0.x = fmaxf(a0.x + bv[0], 0.f);
        v0.y = fmaxf(a0.y + bv[1], 0.f);
        v0.z = fmaxf(a1.x + bv[2], 0.f);
        v0.w = fmaxf(a1.y + bv[3], 0.f);
        v1.x = fmaxf(a2.x + bv[4], 0.f);
        v1.y = fmaxf(a2.y + bv[5], 0.f);
        v1.z = fmaxf(a3.x + bv[6], 0.f);
        v1.w = fmaxf(a3.y + bv[7], 0.f);
        *(float4*)&out[o]     = v0;
        *(float4*)&out[o + 4] = v1;
    }
}

// ---------------------------------------------------------------------------
// Final convs fused with channel gather (only selected channels computed).
// ---------------------------------------------------------------------------
__global__ void __launch_bounds__(256, 1)
conv3_select(const float* __restrict__ h2o, const float* __restrict__ h2w,
             const float* __restrict__ Wo3, const float* __restrict__ bo3,
             const float* __restrict__ Ww3, const float* __restrict__ bw3,
             float* __restrict__ out)
{
    extern __shared__ float smem[];
    float* ho = smem;                 // 64 * 342  (ci-major, pitch 19)
    float* hw = smem + 64 * 342;
    float* ws = smem + 2 * 64 * 342;  // 576 * 3 selected weights

    const int b   = blockIdx.z;
    const int y0  = blockIdx.y * 16;
    const int x0  = blockIdx.x * 16;
    const int tid = threadIdx.x;
    const int cls = g_cls[b];

    for (int i = tid; i < 576; i += 256) {
        ws[i * 3 + 0] = Wo3[i * 6 + 2 * cls];
        ws[i * 3 + 1] = Wo3[i * 6 + 2 * cls + 1];
        ws[i * 3 + 2] = Ww3[i * 3 + cls];
    }

    const float* po = h2o + (size_t)b * HW * HW * 64;
    const float* pw = h2w + (size_t)b * HW * HW * 64;
    for (int i = tid; i < 324 * 16; i += 256) {
        int ci4 = i & 15;
        int rc  = i >> 4;
        int r = rc / 18, c = rc % 18;
        int gy = y0 + r - 1, gx = x0 + c - 1;
        float4 vo = make_float4(0.f, 0.f, 0.f, 0.f);
        float4 vw = vo;
        if ((unsigned)gy < HW && (unsigned)gx < HW) {
            size_t g = ((size_t)gy * HW + gx) * 64 + ci4 * 4;
            vo = *(const float4*)&po[g];
            vw = *(const float4*)&pw[g];
        }
        int base = r * 19 + c;
        ho[(ci4 * 4 + 0) * 342 + base] = vo.x;
        ho[(ci4 * 4 + 1) * 342 + base] = vo.y;
        ho[(ci4 * 4 + 2) * 342 + base] = vo.z;
        ho[(ci4 * 4 + 3) * 342 + base] = vo.w;
        hw[(ci4 * 4 + 0) * 342 + base] = vw.x;
        hw[(ci4 * 4 + 1) * 342 + base] = vw.y;
        hw[(ci4 * 4 + 2) * 342 + base] = vw.z;
        hw[(ci4 * 4 + 3) * 342 + base] = vw.w;
    }
    __syncthreads();

    const int r = tid >> 4, c = tid & 15;
    float o0 = bo3[2 * cls], o1 = bo3[2 * cls + 1], wv = bw3[cls];

#pragma unroll 1
    for (int ky = 0; ky < 3; ++ky) {
#pragma unroll 1
        for (int kx = 0; kx < 3; ++kx) {
            int base = (r + ky) * 19 + (c + kx);
            const float* wp = &ws[(ky * 3 + kx) * 64 * 3];
#pragma unroll 8
            for (int ci = 0; ci < 64; ++ci) {
                float ao = ho[ci * 342 + base];
                float aw = hw[ci * 342 + base];
                o0 = fmaf(ao, wp[ci * 3 + 0], o0);
                o1 = fmaf(ao, wp[ci * 3 + 1], o1);
                wv = fmaf(aw, wp[ci * 3 + 2], wv);
            }
        }
    }

    int gy = y0 + r, gx = x0 + c;
    size_t pix = ((size_t)b * HW + gy) * HW + gx;
    *(float2*)&out[pix * 2] = make_float2(o0, o1);
    out[(size_t)B * HW * HW * 2 + pix] = wv;
}

// ---------------------------------------------------------------------------
extern "C" void kernel_launch(void* const* d_in, const int* in_sizes, int n_in,
                              void* d_out, int out_size)
{
    (void)in_sizes; (void)n_in; (void)out_size;
    const float* x0  = (const float*)d_in[0];
    const float* f4  = (const float*)d_in[1];
    const float* Wo1 = (const float*)d_in[2];
    const float* bo1 = (const float*)d_in[3];
    const float* Wo2 = (const float*)d_in[4];
    const float* bo2 = (const float*)d_in[5];
    const float* Wo3 = (const float*)d_in[6];
    const float* bo3 = (const float*)d_in[7];
    const float* Ww1 = (const float*)d_in[8];
    const float* bw1 = (const float*)d_in[9];
    const float* Ww2 = (const float*)d_in[10];
    const float* bw2 = (const float*)d_in[11];
    const float* Ww3 = (const float*)d_in[12];
    const float* bw3 = (const float*)d_in[13];
    const float* Wc1 = (const float*)d_in[14];
    const float* bc1 = (const float*)d_in[15];
    const float* Wc2 = (const float*)d_in[16];
    const float* bc2 = (const float*)d_in[17];
    const float* Wc3 = (const float*)d_in[18];
    const float* bc3 = (const float*)d_in[19];
    float* out = (float*)d_out;

    void *pA, *pB, *pC;
    cudaGetSymbolAddress(&pA, g_bufA);
    cudaGetSymbolAddress(&pB, g_bufB);
    cudaGetSymbolAddress(&pC, g_bufC);
    float* bufA = (float*)pA;
    float* bufB = (float*)pB;
    float* bufC = (float*)pC;

    const size_t smem32 = (size_t)(324 * (2 * 32 + 2) + 9 * 16 * 64) * sizeof(float); // 122.4 KB
    const size_t smem64 = (size_t)(324 * (2 * 64 + 2) + 9 * 16 * 64) * sizeof(float); // 205.3 KB
    const size_t smem3  = (size_t)(2 * 64 * 342 + 576 * 3) * sizeof(float);           // 182.0 KB

    cudaFuncSetAttribute(conv3x3_relu64<32>, cudaFuncAttributeMaxDynamicSharedMemorySize, (int)smem32);
    cudaFuncSetAttribute(conv3x3_relu64<64>, cudaFuncAttributeMaxDynamicSharedMemorySize, (int)smem64);
    cudaFuncSetAttribute(conv3_select,       cudaFuncAttributeMaxDynamicSharedMemorySize, (int)smem3);

    float* pred = out + (size_t)B * HW * HW * 3;

    head_kernel<<<B, 256>>>(f4, Wc1, bc1, Wc2, bc2, Wc3, bc3, pred);

    dim3 grid(HW / 16, HW / 16, B);
    conv3x3_relu64<32><<<grid, 256, smem32>>>(x0, Wo1, bo1, bufA);   // offsets L1
    conv3x3_relu64<32><<<grid, 256, smem32>>>(x0, Ww1, bw1, bufB);   // weights L1
    conv3x3_relu64<64><<<grid, 256, smem64>>>(bufA, Wo2, bo2, bufC); // offsets L2
    conv3x3_relu64<64><<<grid, 256, smem64>>>(bufB, Ww2, bw2, bufA); // weights L2
    conv3_select<<<grid, 256, smem3>>>(bufC, bufA, Wo3, bo3, Ww3, bw3, out);
}